// round 9
// baseline (speedup 1.0000x reference)
#include <cuda_runtime.h>

// FFF (fast feedforward) sparse tree-walk, round 9.
// Inputs (metadata order):
//   d_in[0]: oldx  [8192, 768]  float32
//   d_in[1]: w_in  [4095, 768]  float32
//   d_in[2]: w_out [768, 4095]  float32
// Output: [8192, 768] float32
//
//   kA (fused): blocks [0,1024) run the per-token decision walk (writes
//               acts[12] + leaf scratch); blocks [1024,4096) transpose w_out
//               into node-major scratch. Independent work, overlapped.
//   kB: accum — 6 warps/token, MLP=12 gathered accumulation.

#define FFF_B       8192
#define FFF_D       768
#define FFF_NODES   4095
#define FFF_DEPTH   11
#define FFF_LEVELS  (FFF_DEPTH + 1)      // 12 nodes on the path
#define FFF_ROW4    (FFF_D / 4)          // 192 float4 per 768-float row

#define DECIDE_BLOCKS 1024               // 8 warp-tokens per block
#define TRANS_BX      128                // ceil(4095/32)
#define TRANS_BY      24                 // 768/32
#define TRANS_BLOCKS  (TRANS_BX * TRANS_BY)

// Scratch: transposed w_out (node-major), per-token activations + leaf.
__device__ float    g_wout_t[(size_t)FFF_NODES * FFF_D];
__device__ float    g_acts[(size_t)FFF_B * FFF_LEVELS];
__device__ unsigned g_leaf[FFF_B];

__device__ __forceinline__ float fff_warp_sum(float v) {
    #pragma unroll
    for (int off = 16; off > 0; off >>= 1)
        v += __shfl_xor_sync(0xffffffffu, v, off);
    return v;
}

// ---------------------------------------------------------------------------
// kA: fused decide + transpose. Decide blocks first (longest pole), transpose
// blocks behind them soak LSU/issue bubbles with pure streaming work.
// ---------------------------------------------------------------------------
__global__ void __launch_bounds__(256, 5)
fff_fused_kernel(const float* __restrict__ x,
                 const float* __restrict__ w_in,
                 const float* __restrict__ w_out) {
    __shared__ float tile[32][33];

    if (blockIdx.x < DECIDE_BLOCKS) {
        // ------------------- decide path: one warp per token -------------------
        const int warp = (int)(blockIdx.x * 8 + (threadIdx.x >> 5));
        const int lane = threadIdx.x & 31;

        const float4* __restrict__ x4  = reinterpret_cast<const float4*>(x) + (size_t)warp * FFF_ROW4;
        const float4* __restrict__ wi4 = reinterpret_cast<const float4*>(w_in);

        float4 xv[6];
        #pragma unroll
        for (int i = 0; i < 6; i++) xv[i] = x4[i * 32 + lane];

        float mylogit = 0.f;   // lane d holds the level-d logit
        unsigned cur = 0;
        #pragma unroll
        for (int d = 0; d < FFF_LEVELS; d++) {
            const float4* __restrict__ wr = wi4 + (size_t)cur * FFF_ROW4;
            float p0 = 0.f, p1 = 0.f, p2 = 0.f, p3 = 0.f;
            #pragma unroll
            for (int i = 0; i < 6; i += 2) {
                const float4 a = wr[i * 32 + lane];
                const float4 b = wr[(i + 1) * 32 + lane];
                p0 = fmaf(a.x, xv[i].x, p0);
                p1 = fmaf(a.y, xv[i].y, p1);
                p2 = fmaf(a.z, xv[i].z, p2);
                p3 = fmaf(a.w, xv[i].w, p3);
                p0 = fmaf(b.x, xv[i + 1].x, p0);
                p1 = fmaf(b.y, xv[i + 1].y, p1);
                p2 = fmaf(b.z, xv[i + 1].z, p2);
                p3 = fmaf(b.w, xv[i + 1].w, p3);
            }
            const float p = fff_warp_sum((p0 + p1) + (p2 + p3));
            if (lane == d) mylogit = p;
            cur = 2u * cur + 1u + (p > 0.0f ? 1u : 0u);
        }

        // ONE exact-erf gelu (matches jax.nn.gelu approximate=False).
        const float myact = 0.5f * mylogit *
                            (1.0f + erff(mylogit * 0.70710678118654752440f));

        if (lane < FFF_LEVELS) g_acts[(size_t)warp * FFF_LEVELS + lane] = myact;
        if (lane == 0)         g_leaf[warp] = cur + 1u;   // level-12 virtual node + 1
    } else {
        // ------------------- transpose path: 32x32 tile -------------------
        const int b  = (int)blockIdx.x - DECIDE_BLOCKS;
        const int n0 = (b % TRANS_BX) * 32;   // node dim (4095)
        const int o0 = (b / TRANS_BX) * 32;   // output dim (768)
        const int tx = (int)threadIdx.x & 31;
        const int ty = (int)threadIdx.x >> 5; // 0..7

        const int n = n0 + tx;
        #pragma unroll
        for (int j = 0; j < 4; j++) {
            const int o = o0 + ty + j * 8;                 // o < 768 always
            if (n < FFF_NODES) {
                tile[ty + j * 8][tx] = w_out[(size_t)o * FFF_NODES + n];
            }
        }
        __syncthreads();

        const int oo = o0 + tx;                            // always < 768
        #pragma unroll
        for (int j = 0; j < 4; j++) {
            const int nn = n0 + ty + j * 8;
            if (nn < FFF_NODES) {
                g_wout_t[(size_t)nn * FFF_D + oo] = tile[tx][ty + j * 8];
            }
        }
    }
}

// ---------------------------------------------------------------------------
// kB: accum — one warp per 512B output chunk (6 warps per token).
// 12 independent gathered float4 loads per warp (MLP=12), no serial chain.
// ---------------------------------------------------------------------------
__global__ void __launch_bounds__(256, 8)
fff_accum_kernel(float* __restrict__ out) {
    const int gwarp = (int)((blockIdx.x * blockDim.x + threadIdx.x) >> 5);
    const int lane  = threadIdx.x & 31;
    const int tok   = gwarp / 6;                       // 192 chunks = 6 warps/token
    const unsigned chunk = (unsigned)((gwarp % 6) * 32 + lane);

    const float4* __restrict__ wo4 = reinterpret_cast<const float4*>(g_wout_t);
    const unsigned vf = g_leaf[tok];

    // acts: 12 floats = 3 float4 loads (uniform broadcast within the warp).
    const float4* __restrict__ a4 = reinterpret_cast<const float4*>(g_acts) + (size_t)tok * 3;
    const float4 av0 = a4[0], av1 = a4[1], av2 = a4[2];
    float acts[FFF_LEVELS] = {av0.x, av0.y, av0.z, av0.w,
                              av1.x, av1.y, av1.z, av1.w,
                              av2.x, av2.y, av2.z, av2.w};

    float a0 = 0.f, a1 = 0.f, a2 = 0.f, a3 = 0.f;
    #pragma unroll
    for (int d = 0; d < FFF_LEVELS; d++) {
        const unsigned node = (vf >> (FFF_LEVELS - d)) - 1u;
        const float4 w = wo4[node * (unsigned)FFF_ROW4 + chunk];  // independent gathers
        a0 = fmaf(acts[d], w.x, a0);
        a1 = fmaf(acts[d], w.y, a1);
        a2 = fmaf(acts[d], w.z, a2);
        a3 = fmaf(acts[d], w.w, a3);
    }

    float4* __restrict__ o4 = reinterpret_cast<float4*>(out) + (size_t)tok * FFF_ROW4;
    o4[chunk] = make_float4(a0, a1, a2, a3);
}

extern "C" void kernel_launch(void* const* d_in, const int* in_sizes, int n_in,
                              void* d_out, int out_size) {
    const float* x     = (const float*)d_in[0];
    const float* w_in  = (const float*)d_in[1];
    const float* w_out = (const float*)d_in[2];
    float* out = (float*)d_out;

    // kA: fused decide (blocks 0..1023) + w_out transpose (blocks 1024..4095).
    {
        const int blocks = DECIDE_BLOCKS + TRANS_BLOCKS;   // 4096
        fff_fused_kernel<<<blocks, 256>>>(x, w_in, w_out);
    }

    // kB: accumulation — 6 warps per token, 8 warps per block.
    {
        const int total_warps = FFF_B * 6;             // 49152
        const int blocks = total_warps / 8;            // 6144 blocks
        fff_accum_kernel<<<blocks, 256>>>(out);
    }
}

// round 10
// speedup vs baseline: 1.0908x; 1.0908x over previous
#include <cuda_runtime.h>

// FFF (fast feedforward) sparse tree-walk, round 10.
// Inputs (metadata order):
//   d_in[0]: oldx  [8192, 768]  float32
//   d_in[1]: w_in  [4095, 768]  float32
//   d_in[2]: w_out [768, 4095]  float32
// Output: [8192, 768] float32
//
//   kA (fused, 64-reg cap): blocks [0,1024) = per-token decision walk;
//       blocks [1024,4096) = w_out transpose (streaming filler work).
//   kB: accum — 3 warps/token, 2 chunks/warp, 24 independent gathers (MLP=24).

#define FFF_B       8192
#define FFF_D       768
#define FFF_NODES   4095
#define FFF_DEPTH   11
#define FFF_LEVELS  (FFF_DEPTH + 1)      // 12 nodes on the path
#define FFF_ROW4    (FFF_D / 4)          // 192 float4 per 768-float row

#define DECIDE_BLOCKS 1024               // 8 warp-tokens per block
#define TRANS_BX      128                // ceil(4095/32)
#define TRANS_BY      24                 // 768/32
#define TRANS_BLOCKS  (TRANS_BX * TRANS_BY)

// Scratch: transposed w_out (node-major), per-token activations + leaf.
__device__ float    g_wout_t[(size_t)FFF_NODES * FFF_D];
__device__ float    g_acts[(size_t)FFF_B * FFF_LEVELS];
__device__ unsigned g_leaf[FFF_B];

__device__ __forceinline__ float fff_warp_sum(float v) {
    #pragma unroll
    for (int off = 16; off > 0; off >>= 1)
        v += __shfl_xor_sync(0xffffffffu, v, off);
    return v;
}

// ---------------------------------------------------------------------------
// kA: fused decide + transpose at decide's natural 64-reg budget.
// ---------------------------------------------------------------------------
__global__ void __launch_bounds__(256, 4)
fff_fused_kernel(const float* __restrict__ x,
                 const float* __restrict__ w_in,
                 const float* __restrict__ w_out) {
    __shared__ float tile[32][33];

    if (blockIdx.x < DECIDE_BLOCKS) {
        // ------------------- decide path: one warp per token -------------------
        const int warp = (int)(blockIdx.x * 8 + (threadIdx.x >> 5));
        const int lane = threadIdx.x & 31;

        const float4* __restrict__ x4  = reinterpret_cast<const float4*>(x) + (size_t)warp * FFF_ROW4;
        const float4* __restrict__ wi4 = reinterpret_cast<const float4*>(w_in);

        float4 xv[6];
        #pragma unroll
        for (int i = 0; i < 6; i++) xv[i] = x4[i * 32 + lane];

        float mylogit = 0.f;   // lane d holds the level-d logit
        unsigned cur = 0;
        #pragma unroll
        for (int d = 0; d < FFF_LEVELS; d++) {
            const float4* __restrict__ wr = wi4 + (size_t)cur * FFF_ROW4;
            float p0 = 0.f, p1 = 0.f, p2 = 0.f, p3 = 0.f;
            #pragma unroll
            for (int i = 0; i < 6; i += 2) {
                const float4 a = wr[i * 32 + lane];
                const float4 b = wr[(i + 1) * 32 + lane];
                p0 = fmaf(a.x, xv[i].x, p0);
                p1 = fmaf(a.y, xv[i].y, p1);
                p2 = fmaf(a.z, xv[i].z, p2);
                p3 = fmaf(a.w, xv[i].w, p3);
                p0 = fmaf(b.x, xv[i + 1].x, p0);
                p1 = fmaf(b.y, xv[i + 1].y, p1);
                p2 = fmaf(b.z, xv[i + 1].z, p2);
                p3 = fmaf(b.w, xv[i + 1].w, p3);
            }
            const float p = fff_warp_sum((p0 + p1) + (p2 + p3));
            if (lane == d) mylogit = p;
            cur = 2u * cur + 1u + (p > 0.0f ? 1u : 0u);
        }

        // ONE exact-erf gelu (matches jax.nn.gelu approximate=False).
        const float myact = 0.5f * mylogit *
                            (1.0f + erff(mylogit * 0.70710678118654752440f));

        if (lane < FFF_LEVELS) g_acts[(size_t)warp * FFF_LEVELS + lane] = myact;
        if (lane == 0)         g_leaf[warp] = cur + 1u;   // level-12 virtual node + 1
    } else {
        // ------------------- transpose path: 32x32 tile -------------------
        const int b  = (int)blockIdx.x - DECIDE_BLOCKS;
        const int n0 = (b % TRANS_BX) * 32;   // node dim (4095)
        const int o0 = (b / TRANS_BX) * 32;   // output dim (768)
        const int tx = (int)threadIdx.x & 31;
        const int ty = (int)threadIdx.x >> 5; // 0..7

        const int n = n0 + tx;
        #pragma unroll
        for (int j = 0; j < 4; j++) {
            const int o = o0 + ty + j * 8;                 // o < 768 always
            if (n < FFF_NODES) {
                tile[ty + j * 8][tx] = w_out[(size_t)o * FFF_NODES + n];
            }
        }
        __syncthreads();

        const int oo = o0 + tx;                            // always < 768
        #pragma unroll
        for (int j = 0; j < 4; j++) {
            const int nn = n0 + ty + j * 8;
            if (nn < FFF_NODES) {
                g_wout_t[(size_t)nn * FFF_D + oo] = tile[tx][ty + j * 8];
            }
        }
    }
}

// ---------------------------------------------------------------------------
// kB: accum — one warp per TWO 512B output chunks (3 warps per token).
// 24 independent gathered float4 loads per warp (MLP=24), no serial chain.
// ---------------------------------------------------------------------------
__global__ void __launch_bounds__(256, 4)
fff_accum_kernel(float* __restrict__ out) {
    const int gwarp = (int)((blockIdx.x * blockDim.x + threadIdx.x) >> 5);
    const int lane  = threadIdx.x & 31;
    const int tok   = gwarp / 3;                  // 3 warps per token
    const int pair  = gwarp % 3;                  // covers chunks [pair*64, pair*64+64)
    const unsigned c0 = (unsigned)(pair * 64 + lane);
    const unsigned c1 = c0 + 32u;

    const float4* __restrict__ wo4 = reinterpret_cast<const float4*>(g_wout_t);
    const unsigned vf = g_leaf[tok];

    // acts: 12 floats = 3 float4 loads (uniform broadcast within the warp).
    const float4* __restrict__ a4 = reinterpret_cast<const float4*>(g_acts) + (size_t)tok * 3;
    const float4 av0 = a4[0], av1 = a4[1], av2 = a4[2];
    const float acts[FFF_LEVELS] = {av0.x, av0.y, av0.z, av0.w,
                                    av1.x, av1.y, av1.z, av1.w,
                                    av2.x, av2.y, av2.z, av2.w};

    float a00 = 0.f, a01 = 0.f, a02 = 0.f, a03 = 0.f;
    float a10 = 0.f, a11 = 0.f, a12 = 0.f, a13 = 0.f;
    #pragma unroll
    for (int d = 0; d < FFF_LEVELS; d++) {
        const unsigned base = ((vf >> (FFF_LEVELS - d)) - 1u) * (unsigned)FFF_ROW4;
        const float4 w0 = wo4[base + c0];          // 24 independent gathers total
        const float4 w1 = wo4[base + c1];
        const float ad = acts[d];
        a00 = fmaf(ad, w0.x, a00);
        a01 = fmaf(ad, w0.y, a01);
        a02 = fmaf(ad, w0.z, a02);
        a03 = fmaf(ad, w0.w, a03);
        a10 = fmaf(ad, w1.x, a10);
        a11 = fmaf(ad, w1.y, a11);
        a12 = fmaf(ad, w1.z, a12);
        a13 = fmaf(ad, w1.w, a13);
    }

    float4* __restrict__ o4 = reinterpret_cast<float4*>(out) + (size_t)tok * FFF_ROW4;
    o4[c0] = make_float4(a00, a01, a02, a03);
    o4[c1] = make_float4(a10, a11, a12, a13);
}

extern "C" void kernel_launch(void* const* d_in, const int* in_sizes, int n_in,
                              void* d_out, int out_size) {
    const float* x     = (const float*)d_in[0];
    const float* w_in  = (const float*)d_in[1];
    const float* w_out = (const float*)d_in[2];
    float* out = (float*)d_out;

    // kA: fused decide (blocks 0..1023) + w_out transpose (blocks 1024..4095).
    {
        const int blocks = DECIDE_BLOCKS + TRANS_BLOCKS;   // 4096
        fff_fused_kernel<<<blocks, 256>>>(x, w_in, w_out);
    }

    // kB: accumulation — 3 warps per token, 8 warps per block.
    {
        const int total_warps = FFF_B * 3;             // 24576
        const int blocks = total_warps / 8;            // 3072 blocks
        fff_accum_kernel<<<blocks, 256>>>(out);
    }
}